// round 8
// baseline (speedup 1.0000x reference)
#include <cuda_runtime.h>
#include <cuda_fp16.h>

// LightGCN: out = (x + A@x + A@A@x + A@A@A@x) / 4, COO -> per-call CSR build,
// then gather SpMM (fp16 intermediates), layer 3 fused with mean.
// R8: TWO warps per row (64 dims each, 4B gathers) -> smaller loop body,
// ~75% occupancy, 2x in-flight gathers per SM. Attacks the 48% issue ceiling
// seen in R6/R7 profiles (latency-bound, no unit saturated).

#define D        128
#define DU       64          // uint (half2) per feature row
#define MAX_N    100352      // padded to scan-tile multiple; tail stays 0
#define MAX_E    3200000
#define SCAN_TILE 1024       // 256 threads * 4 items
#define MAX_TILES ((MAX_N + SCAN_TILE - 1) / SCAN_TILE)

struct __align__(8) Edge { int c; float v; };

__device__ int    g_count[MAX_N];                    // static zero; memset N/call
__device__ int    g_offs[MAX_E];
__device__ int    g_rowptr[MAX_N + 1];
__device__ unsigned long long g_tile_state[MAX_TILES];
__device__ __align__(16) Edge g_edges[MAX_E];
__device__ __half g_xh [(size_t)MAX_N * D];
__device__ __half g_b1h[(size_t)MAX_N * D];
__device__ __half g_b2h[(size_t)MAX_N * D];

// ----------------------------------------- fused convert (blocks [0,CB)) + hist

__global__ void hist_convert_kernel(const float4* __restrict__ x,
                                    uint2* __restrict__ xh, int n4,
                                    const int* __restrict__ rows, int E,
                                    int conv_blocks) {
    if (blockIdx.x < conv_blocks) {
        int stride = conv_blocks * blockDim.x;
        for (int i = blockIdx.x * blockDim.x + threadIdx.x; i < n4; i += stride) {
            float4 v = x[i];
            uint2 o;
            *reinterpret_cast<__half2*>(&o.x) = __floats2half2_rn(v.x, v.y);
            *reinterpret_cast<__half2*>(&o.y) = __floats2half2_rn(v.z, v.w);
            xh[i] = o;
        }
    } else {
        int i = (blockIdx.x - conv_blocks) * blockDim.x + threadIdx.x;
        if (i < E) g_offs[i] = atomicAdd(&g_count[rows[i]], 1);
    }
}

// --------------------------------------- single-pass scan (decoupled lookback)

// Tile state: bits[32+] = status (0 invalid, 1 aggregate, 2 inclusive),
// bits[31:0] = value. One 64-bit store publishes both atomically.
__global__ void scan_kernel(int n, int E) {
    __shared__ int s_warp[8];
    __shared__ int s_prefix;
    int tile = blockIdx.x;
    int t = threadIdx.x;
    int lane = t & 31, wid = t >> 5;
    int base = tile * SCAN_TILE + t * 4;

    // padded region of g_count is permanently zero -> unguarded int4 load OK
    int4 c = *reinterpret_cast<const int4*>(&g_count[base]);
    int sum = c.x + c.y + c.z + c.w;

    // warp inclusive scan of per-thread sums
    int v = sum;
    #pragma unroll
    for (int off = 1; off < 32; off <<= 1) {
        int tv = __shfl_up_sync(0xffffffffu, v, off);
        if (lane >= off) v += tv;
    }
    if (lane == 31) s_warp[wid] = v;
    __syncthreads();
    if (wid == 0) {
        int wv = (lane < 8) ? s_warp[lane] : 0;
        #pragma unroll
        for (int off = 1; off < 8; off <<= 1) {
            int tv = __shfl_up_sync(0xffffffffu, wv, off);
            if (lane >= off) wv += tv;
        }
        if (lane < 8) s_warp[lane] = wv;
    }
    __syncthreads();
    int block_total = s_warp[7];
    int thr_excl = ((wid ? s_warp[wid - 1] : 0)) + v - sum;

    // publish aggregate (tile 0 publishes inclusive directly)
    if (t == 0) {
        unsigned long long st = (tile == 0)
            ? ((2ULL << 32) | (unsigned int)block_total)
            : ((1ULL << 32) | (unsigned int)block_total);
        atomicExch(&g_tile_state[tile], st);
        if (tile == 0) s_prefix = 0;
    }

    // warp 0 performs warp-parallel lookback
    if (tile > 0 && wid == 0) {
        int prefix = 0;
        int windowEnd = tile;
        for (;;) {
            int idx = windowEnd - 1 - lane;
            unsigned long long st;
            if (idx >= 0) {
                do { st = atomicAdd(&g_tile_state[idx], 0ULL); }
                while ((st >> 32) == 0ULL);
            } else {
                st = (2ULL << 32);             // virtual inclusive 0
            }
            unsigned status = (unsigned)(st >> 32);
            int val = (int)(unsigned)st;
            unsigned ballot = __ballot_sync(0xffffffffu, status == 2u);
            int firstIncl = __ffs(ballot) - 1;
            int contrib;
            if (ballot) contrib = (lane <= firstIncl) ? val : 0;
            else        contrib = val;
            #pragma unroll
            for (int off = 16; off > 0; off >>= 1)
                contrib += __shfl_down_sync(0xffffffffu, contrib, off);
            contrib = __shfl_sync(0xffffffffu, contrib, 0);
            prefix += contrib;
            if (ballot) break;
            windowEnd -= 32;
        }
        if (lane == 0) {
            s_prefix = prefix;
            atomicExch(&g_tile_state[tile],
                       (2ULL << 32) | (unsigned int)(prefix + block_total));
        }
    }
    __syncthreads();
    int prefix = s_prefix;

    // exclusive rowptr; index n (count 0) lands rowptr[n] = E automatically
    int p0 = prefix + thr_excl;
    int4 o;
    o.x = p0;
    o.y = p0 + c.x;
    o.z = p0 + c.x + c.y;
    o.w = p0 + c.x + c.y + c.z;
    if (base + 3 <= n) {
        *reinterpret_cast<int4*>(&g_rowptr[base]) = o;
    } else {
        if (base     <= n) g_rowptr[base]     = o.x;
        if (base + 1 <= n) g_rowptr[base + 1] = o.y;
        if (base + 2 <= n) g_rowptr[base + 2] = o.z;
        if (base + 3 <= n) g_rowptr[base + 3] = o.w;
    }
}

// ---------------------------------------------------------------- scatter

// Atomic-free: slot = rowptr[row] + precomputed within-row offset.
__global__ void scatter_kernel(const int* __restrict__ rows,
                               const int* __restrict__ cols,
                               const float* __restrict__ vals, int E) {
    int i = blockIdx.x * blockDim.x + threadIdx.x;
    if (i < E) {
        int pos = g_rowptr[rows[i]] + g_offs[i];
        Edge e;
        e.c = cols[i];
        e.v = vals[i];
        g_edges[pos] = e;
    }
}

// ---------------------------------------------------------------- SpMM (half)

// Half-row accumulate: lane owns dims [2*off, 2*off+2) where off = half*32+lane.
__device__ __forceinline__ void gfma(float2& acc, float v, unsigned t) {
    float2 f = __half22float2(*reinterpret_cast<const __half2*>(&t));
    acc.x += v * f.x;
    acc.y += v * f.y;
}

// Two warps per row (half = 0/1). Per edge: 4B gather (128B/warp, 1 wavefront),
// edges pair-loaded as uint4 broadcast (shared L1 line with sibling warp).
__device__ __forceinline__ float2 spmm_half_row(const unsigned* __restrict__ src,
                                                int row, int off) {
    int beg = g_rowptr[row];
    int end = g_rowptr[row + 1];
    float2 acc = make_float2(0.f, 0.f);
    int i = beg;

    if ((i & 1) && i < end) {
        Edge e = g_edges[i];
        gfma(acc, e.v, __ldg(src + (size_t)e.c * DU + off));
        ++i;
    }

    for (; i + 8 <= end; i += 8) {
        uint4 p0 = *reinterpret_cast<const uint4*>(&g_edges[i]);
        uint4 p1 = *reinterpret_cast<const uint4*>(&g_edges[i + 2]);
        uint4 p2 = *reinterpret_cast<const uint4*>(&g_edges[i + 4]);
        uint4 p3 = *reinterpret_cast<const uint4*>(&g_edges[i + 6]);
        unsigned t0 = __ldg(src + (size_t)(int)p0.x * DU + off);
        unsigned t1 = __ldg(src + (size_t)(int)p0.z * DU + off);
        unsigned t2 = __ldg(src + (size_t)(int)p1.x * DU + off);
        unsigned t3 = __ldg(src + (size_t)(int)p1.z * DU + off);
        unsigned t4 = __ldg(src + (size_t)(int)p2.x * DU + off);
        unsigned t5 = __ldg(src + (size_t)(int)p2.z * DU + off);
        unsigned t6 = __ldg(src + (size_t)(int)p3.x * DU + off);
        unsigned t7 = __ldg(src + (size_t)(int)p3.z * DU + off);
        gfma(acc, __uint_as_float(p0.y), t0);
        gfma(acc, __uint_as_float(p0.w), t1);
        gfma(acc, __uint_as_float(p1.y), t2);
        gfma(acc, __uint_as_float(p1.w), t3);
        gfma(acc, __uint_as_float(p2.y), t4);
        gfma(acc, __uint_as_float(p2.w), t5);
        gfma(acc, __uint_as_float(p3.y), t6);
        gfma(acc, __uint_as_float(p3.w), t7);
    }

    for (; i + 2 <= end; i += 2) {
        uint4 p = *reinterpret_cast<const uint4*>(&g_edges[i]);
        unsigned t0 = __ldg(src + (size_t)(int)p.x * DU + off);
        unsigned t1 = __ldg(src + (size_t)(int)p.z * DU + off);
        gfma(acc, __uint_as_float(p.y), t0);
        gfma(acc, __uint_as_float(p.w), t1);
    }

    if (i < end) {
        Edge e = g_edges[i];
        gfma(acc, e.v, __ldg(src + (size_t)e.c * DU + off));
    }
    return acc;
}

// Block of 256 threads = 8 warps = 4 rows (2 warps/row, same block -> shared L1).
__global__ void __launch_bounds__(256, 6)
spmm_h_kernel(const unsigned* __restrict__ src,
              unsigned* __restrict__ dst, int n) {
    int gw = (blockIdx.x * blockDim.x + threadIdx.x) >> 5;   // global warp
    int row = gw >> 1;
    if (row >= n) return;
    int off = ((gw & 1) << 5) | (threadIdx.x & 31);          // 0..63
    float2 acc = spmm_half_row(src, row, off);
    unsigned o;
    *reinterpret_cast<__half2*>(&o) = __floats2half2_rn(acc.x, acc.y);
    dst[(size_t)row * DU + off] = o;
}

// Layer 3 fused with the mean: out = 0.25 * (x + b1 + b2 + A@b2)
__global__ void __launch_bounds__(256, 6)
spmm_final_kernel(const unsigned* __restrict__ b2,
                  const float2* __restrict__ x,
                  const unsigned* __restrict__ b1,
                  float2* __restrict__ out, int n) {
    int gw = (blockIdx.x * blockDim.x + threadIdx.x) >> 5;
    int row = gw >> 1;
    if (row >= n) return;
    int off = ((gw & 1) << 5) | (threadIdx.x & 31);
    float2 acc = spmm_half_row(b2, row, off);

    size_t idx = (size_t)row * DU + off;
    float2 xv = x[idx];
    float2 a = __half22float2(*reinterpret_cast<const __half2*>(&b1[idx]));
    float2 c = __half22float2(*reinterpret_cast<const __half2*>(&b2[idx]));

    float2 o;
    o.x = 0.25f * (xv.x + a.x + c.x + acc.x);
    o.y = 0.25f * (xv.y + a.y + c.y + acc.y);
    out[idx] = o;
}

// ---------------------------------------------------------------- launch

extern "C" void kernel_launch(void* const* d_in, const int* in_sizes, int n_in,
                              void* d_out, int out_size) {
    const float* x  = (const float*)d_in[0];
    const int*   er = (const int*)d_in[1];
    const int*   ec = (const int*)d_in[2];
    const float* ev = (const float*)d_in[3];

    int E = in_sizes[1];
    int N = in_sizes[0] / D;

    void *xhp, *b1p, *b2p, *cntp, *tsp;
    cudaGetSymbolAddress(&xhp, g_xh);
    cudaGetSymbolAddress(&b1p, g_b1h);
    cudaGetSymbolAddress(&b2p, g_b2h);
    cudaGetSymbolAddress(&cntp, g_count);
    cudaGetSymbolAddress(&tsp, g_tile_state);

    const int TPB = 256;
    int n4 = N * (D / 4);                             // float4 count of x
    int ntiles = (N + SCAN_TILE) / SCAN_TILE;         // covers index N too

    cudaMemsetAsync(cntp, 0, (size_t)N * sizeof(int));
    cudaMemsetAsync(tsp, 0, (size_t)ntiles * sizeof(unsigned long long));

    // convert (first conv_blocks, grid-stride) runs concurrently with hist
    const int conv_blocks = 1024;
    int edge_blocks = (E + TPB - 1) / TPB;
    hist_convert_kernel<<<conv_blocks + edge_blocks, TPB>>>(
        (const float4*)x, (uint2*)xhp, n4, er, E, conv_blocks);

    scan_kernel<<<ntiles, TPB>>>(N, E);

    scatter_kernel<<<edge_blocks, TPB>>>(er, ec, ev, E);

    // 3 propagation layers (layer 3 fused with final mean); 2 warps per row
    int spmm_blocks = (N * 64 + TPB - 1) / TPB;
    spmm_h_kernel<<<spmm_blocks, TPB>>>((const unsigned*)xhp,
                                        (unsigned*)b1p, N);
    spmm_h_kernel<<<spmm_blocks, TPB>>>((const unsigned*)b1p,
                                        (unsigned*)b2p, N);
    spmm_final_kernel<<<spmm_blocks, TPB>>>((const unsigned*)b2p,
                                            (const float2*)x,
                                            (const unsigned*)b1p,
                                            (float2*)d_out, N);
}

// round 9
// speedup vs baseline: 1.3252x; 1.3252x over previous
#include <cuda_runtime.h>
#include <cuda_fp16.h>

// LightGCN: out = (x + A@x + A@A@x + A@A@A@x) / 4, COO -> per-call CSR build,
// then warp-per-row gather SpMM (fp16 intermediates), layer 3 fused with mean.
// R9: SpMM = R7 structure (measured at ~93% of LTS byte cap) with 128-thread
// blocks for tail balance; preprocessing attacked instead: 4-edge/thread
// atomic-free scatter (independent chains), vectorized hist.

#define D        128
#define DV       32          // float4 per row
#define MAX_N    100352      // padded to scan-tile multiple; tail stays 0
#define MAX_E    3200000
#define SCAN_TILE 1024       // 256 threads * 4 items
#define MAX_TILES ((MAX_N + SCAN_TILE - 1) / SCAN_TILE)

struct __align__(8) Edge { int c; float v; };

__device__ int    g_count[MAX_N];                    // static zero; memset N/call
__device__ __align__(16) int g_offs[MAX_E];
__device__ int    g_rowptr[MAX_N + 1];
__device__ unsigned long long g_tile_state[MAX_TILES];
__device__ __align__(16) Edge g_edges[MAX_E];
__device__ __half g_xh [(size_t)MAX_N * D];
__device__ __half g_b1h[(size_t)MAX_N * D];
__device__ __half g_b2h[(size_t)MAX_N * D];

// ----------------------------------------- fused convert (blocks [0,CB)) + hist

// Hist threads process 4 edges each (int4 row loads, 4 independent atomics,
// int4 offs store). Thread e4 handles the scalar tail.
__global__ void hist_convert_kernel(const float4* __restrict__ x,
                                    uint2* __restrict__ xh, int n4,
                                    const int* __restrict__ rows, int E,
                                    int conv_blocks) {
    if (blockIdx.x < conv_blocks) {
        int stride = conv_blocks * blockDim.x;
        for (int i = blockIdx.x * blockDim.x + threadIdx.x; i < n4; i += stride) {
            float4 v = x[i];
            uint2 o;
            *reinterpret_cast<__half2*>(&o.x) = __floats2half2_rn(v.x, v.y);
            *reinterpret_cast<__half2*>(&o.y) = __floats2half2_rn(v.z, v.w);
            xh[i] = o;
        }
    } else {
        int e4 = E >> 2;
        int i = (blockIdx.x - conv_blocks) * blockDim.x + threadIdx.x;
        if (i < e4) {
            int4 r = reinterpret_cast<const int4*>(rows)[i];
            int4 o;
            o.x = atomicAdd(&g_count[r.x], 1);
            o.y = atomicAdd(&g_count[r.y], 1);
            o.z = atomicAdd(&g_count[r.z], 1);
            o.w = atomicAdd(&g_count[r.w], 1);
            reinterpret_cast<int4*>(g_offs)[i] = o;
        } else if (i == e4) {
            for (int t = e4 * 4; t < E; ++t)
                g_offs[t] = atomicAdd(&g_count[rows[t]], 1);
        }
    }
}

// --------------------------------------- single-pass scan (decoupled lookback)

// Tile state: bits[32+] = status (0 invalid, 1 aggregate, 2 inclusive),
// bits[31:0] = value. One 64-bit store publishes both atomically.
__global__ void scan_kernel(int n, int E) {
    __shared__ int s_warp[8];
    __shared__ int s_prefix;
    int tile = blockIdx.x;
    int t = threadIdx.x;
    int lane = t & 31, wid = t >> 5;
    int base = tile * SCAN_TILE + t * 4;

    // padded region of g_count is permanently zero -> unguarded int4 load OK
    int4 c = *reinterpret_cast<const int4*>(&g_count[base]);
    int sum = c.x + c.y + c.z + c.w;

    // warp inclusive scan of per-thread sums
    int v = sum;
    #pragma unroll
    for (int off = 1; off < 32; off <<= 1) {
        int tv = __shfl_up_sync(0xffffffffu, v, off);
        if (lane >= off) v += tv;
    }
    if (lane == 31) s_warp[wid] = v;
    __syncthreads();
    if (wid == 0) {
        int wv = (lane < 8) ? s_warp[lane] : 0;
        #pragma unroll
        for (int off = 1; off < 8; off <<= 1) {
            int tv = __shfl_up_sync(0xffffffffu, wv, off);
            if (lane >= off) wv += tv;
        }
        if (lane < 8) s_warp[lane] = wv;
    }
    __syncthreads();
    int block_total = s_warp[7];
    int thr_excl = ((wid ? s_warp[wid - 1] : 0)) + v - sum;

    // publish aggregate (tile 0 publishes inclusive directly)
    if (t == 0) {
        unsigned long long st = (tile == 0)
            ? ((2ULL << 32) | (unsigned int)block_total)
            : ((1ULL << 32) | (unsigned int)block_total);
        atomicExch(&g_tile_state[tile], st);
        if (tile == 0) s_prefix = 0;
    }

    // warp 0 performs warp-parallel lookback
    if (tile > 0 && wid == 0) {
        int prefix = 0;
        int windowEnd = tile;
        for (;;) {
            int idx = windowEnd - 1 - lane;
            unsigned long long st;
            if (idx >= 0) {
                do { st = atomicAdd(&g_tile_state[idx], 0ULL); }
                while ((st >> 32) == 0ULL);
            } else {
                st = (2ULL << 32);             // virtual inclusive 0
            }
            unsigned status = (unsigned)(st >> 32);
            int val = (int)(unsigned)st;
            unsigned ballot = __ballot_sync(0xffffffffu, status == 2u);
            int firstIncl = __ffs(ballot) - 1;
            int contrib;
            if (ballot) contrib = (lane <= firstIncl) ? val : 0;
            else        contrib = val;
            #pragma unroll
            for (int off = 16; off > 0; off >>= 1)
                contrib += __shfl_down_sync(0xffffffffu, contrib, off);
            contrib = __shfl_sync(0xffffffffu, contrib, 0);
            prefix += contrib;
            if (ballot) break;
            windowEnd -= 32;
        }
        if (lane == 0) {
            s_prefix = prefix;
            atomicExch(&g_tile_state[tile],
                       (2ULL << 32) | (unsigned int)(prefix + block_total));
        }
    }
    __syncthreads();
    int prefix = s_prefix;

    // exclusive rowptr; index n (count 0) lands rowptr[n] = E automatically
    int p0 = prefix + thr_excl;
    int4 o;
    o.x = p0;
    o.y = p0 + c.x;
    o.z = p0 + c.x + c.y;
    o.w = p0 + c.x + c.y + c.z;
    if (base + 3 <= n) {
        *reinterpret_cast<int4*>(&g_rowptr[base]) = o;
    } else {
        if (base     <= n) g_rowptr[base]     = o.x;
        if (base + 1 <= n) g_rowptr[base + 1] = o.y;
        if (base + 2 <= n) g_rowptr[base + 2] = o.z;
        if (base + 3 <= n) g_rowptr[base + 3] = o.w;
    }
}

// ---------------------------------------------------------------- scatter

// Atomic-free, 4 edges per thread: coalesced int4/float4 inputs, 4 fully
// independent (random rowptr load -> 8B store) chains in flight.
__global__ void scatter_kernel(const int* __restrict__ rows,
                               const int* __restrict__ cols,
                               const float* __restrict__ vals, int E) {
    int e4 = E >> 2;
    int i = blockIdx.x * blockDim.x + threadIdx.x;
    if (i < e4) {
        int4   r = reinterpret_cast<const int4*>(rows)[i];
        int4   c = reinterpret_cast<const int4*>(cols)[i];
        float4 v = reinterpret_cast<const float4*>(vals)[i];
        int4   o = reinterpret_cast<const int4*>(g_offs)[i];
        int p0 = g_rowptr[r.x] + o.x;
        int p1 = g_rowptr[r.y] + o.y;
        int p2 = g_rowptr[r.z] + o.z;
        int p3 = g_rowptr[r.w] + o.w;
        Edge e0; e0.c = c.x; e0.v = v.x; g_edges[p0] = e0;
        Edge e1; e1.c = c.y; e1.v = v.y; g_edges[p1] = e1;
        Edge e2; e2.c = c.z; e2.v = v.z; g_edges[p2] = e2;
        Edge e3; e3.c = c.w; e3.v = v.w; g_edges[p3] = e3;
    } else if (i == e4) {
        for (int t = e4 * 4; t < E; ++t) {
            int pos = g_rowptr[rows[t]] + g_offs[t];
            Edge e; e.c = cols[t]; e.v = vals[t];
            g_edges[pos] = e;
        }
    }
}

// ---------------------------------------------------------------- SpMM (half)

__device__ __forceinline__ void gather_fma(float4& acc, float v, uint2 t) {
    float2 lo = __half22float2(*reinterpret_cast<const __half2*>(&t.x));
    float2 hi = __half22float2(*reinterpret_cast<const __half2*>(&t.y));
    acc.x += v * lo.x;
    acc.y += v * lo.y;
    acc.z += v * hi.x;
    acc.w += v * hi.y;
}

// One warp per output row; lane owns dims [4*lane, 4*lane+4).
// 8 edges in flight per iteration; edges pair-loaded as uint4 (LDG.128, .cs).
__device__ __forceinline__ float4 spmm_row(const uint2* __restrict__ src,
                                           int w, int lane) {
    int beg = g_rowptr[w];
    int end = g_rowptr[w + 1];
    float4 acc = make_float4(0.f, 0.f, 0.f, 0.f);
    int i = beg;

    // align to even index so uint4 pair-loads are 16B aligned
    if ((i & 1) && i < end) {
        Edge e = g_edges[i];
        uint2 t = __ldg(src + (size_t)e.c * DV + lane);
        gather_fma(acc, e.v, t);
        ++i;
    }

    for (; i + 8 <= end; i += 8) {
        uint4 p0 = __ldcs(reinterpret_cast<const uint4*>(&g_edges[i]));
        uint4 p1 = __ldcs(reinterpret_cast<const uint4*>(&g_edges[i + 2]));
        uint4 p2 = __ldcs(reinterpret_cast<const uint4*>(&g_edges[i + 4]));
        uint4 p3 = __ldcs(reinterpret_cast<const uint4*>(&g_edges[i + 6]));
        uint2 t0 = __ldg(src + (size_t)(int)p0.x * DV + lane);
        uint2 t1 = __ldg(src + (size_t)(int)p0.z * DV + lane);
        uint2 t2 = __ldg(src + (size_t)(int)p1.x * DV + lane);
        uint2 t3 = __ldg(src + (size_t)(int)p1.z * DV + lane);
        uint2 t4 = __ldg(src + (size_t)(int)p2.x * DV + lane);
        uint2 t5 = __ldg(src + (size_t)(int)p2.z * DV + lane);
        uint2 t6 = __ldg(src + (size_t)(int)p3.x * DV + lane);
        uint2 t7 = __ldg(src + (size_t)(int)p3.z * DV + lane);
        gather_fma(acc, __uint_as_float(p0.y), t0);
        gather_fma(acc, __uint_as_float(p0.w), t1);
        gather_fma(acc, __uint_as_float(p1.y), t2);
        gather_fma(acc, __uint_as_float(p1.w), t3);
        gather_fma(acc, __uint_as_float(p2.y), t4);
        gather_fma(acc, __uint_as_float(p2.w), t5);
        gather_fma(acc, __uint_as_float(p3.y), t6);
        gather_fma(acc, __uint_as_float(p3.w), t7);
    }

    for (; i + 2 <= end; i += 2) {
        uint4 p = __ldcs(reinterpret_cast<const uint4*>(&g_edges[i]));
        uint2 t0 = __ldg(src + (size_t)(int)p.x * DV + lane);
        uint2 t1 = __ldg(src + (size_t)(int)p.z * DV + lane);
        gather_fma(acc, __uint_as_float(p.y), t0);
        gather_fma(acc, __uint_as_float(p.w), t1);
    }

    if (i < end) {
        Edge e = g_edges[i];
        uint2 t = __ldg(src + (size_t)e.c * DV + lane);
        gather_fma(acc, e.v, t);
    }
    return acc;
}

// 128-thread blocks = 4 warps = 4 rows: finer scheduling granularity.
__global__ void __launch_bounds__(128, 10)
spmm_h_kernel(const uint2* __restrict__ src,
              uint2* __restrict__ dst, int n) {
    int w = (blockIdx.x * blockDim.x + threadIdx.x) >> 5;
    int lane = threadIdx.x & 31;
    if (w >= n) return;
    float4 acc = spmm_row(src, w, lane);
    uint2 o;
    *reinterpret_cast<__half2*>(&o.x) = __floats2half2_rn(acc.x, acc.y);
    *reinterpret_cast<__half2*>(&o.y) = __floats2half2_rn(acc.z, acc.w);
    dst[(size_t)w * DV + lane] = o;
}

// Layer 3 fused with the mean: out = 0.25 * (x + b1 + b2 + A@b2)
__global__ void __launch_bounds__(128, 10)
spmm_final_kernel(const uint2* __restrict__ b2,
                  const float4* __restrict__ x,
                  const uint2* __restrict__ b1,
                  float4* __restrict__ out, int n) {
    int w = (blockIdx.x * blockDim.x + threadIdx.x) >> 5;
    int lane = threadIdx.x & 31;
    if (w >= n) return;
    float4 acc = spmm_row(b2, w, lane);

    size_t idx = (size_t)w * DV + lane;
    float4 xv = x[idx];
    uint2 u1 = b1[idx];
    uint2 u2 = b2[idx];
    float2 a = __half22float2(*reinterpret_cast<const __half2*>(&u1.x));
    float2 b = __half22float2(*reinterpret_cast<const __half2*>(&u1.y));
    float2 c = __half22float2(*reinterpret_cast<const __half2*>(&u2.x));
    float2 d = __half22float2(*reinterpret_cast<const __half2*>(&u2.y));

    float4 o;
    o.x = 0.25f * (xv.x + a.x + c.x + acc.x);
    o.y = 0.25f * (xv.y + a.y + c.y + acc.y);
    o.z = 0.25f * (xv.z + b.x + d.x + acc.z);
    o.w = 0.25f * (xv.w + b.y + d.y + acc.w);
    out[idx] = o;
}

// ---------------------------------------------------------------- launch

extern "C" void kernel_launch(void* const* d_in, const int* in_sizes, int n_in,
                              void* d_out, int out_size) {
    const float* x  = (const float*)d_in[0];
    const int*   er = (const int*)d_in[1];
    const int*   ec = (const int*)d_in[2];
    const float* ev = (const float*)d_in[3];

    int E = in_sizes[1];
    int N = in_sizes[0] / D;

    void *xhp, *b1p, *b2p, *cntp, *tsp;
    cudaGetSymbolAddress(&xhp, g_xh);
    cudaGetSymbolAddress(&b1p, g_b1h);
    cudaGetSymbolAddress(&b2p, g_b2h);
    cudaGetSymbolAddress(&cntp, g_count);
    cudaGetSymbolAddress(&tsp, g_tile_state);

    const int TPB = 256;
    int n4 = N * DV;                                  // float4 count of x
    int e4 = E >> 2;
    int ntiles = (N + SCAN_TILE) / SCAN_TILE;         // covers index N too

    cudaMemsetAsync(cntp, 0, (size_t)N * sizeof(int));
    cudaMemsetAsync(tsp, 0, (size_t)ntiles * sizeof(unsigned long long));

    // convert (first conv_blocks, grid-stride) runs concurrently with hist
    const int conv_blocks = 1024;
    int hist_blocks = (e4 + 1 + TPB - 1) / TPB;
    hist_convert_kernel<<<conv_blocks + hist_blocks, TPB>>>(
        (const float4*)x, (uint2*)xhp, n4, er, E, conv_blocks);

    scan_kernel<<<ntiles, TPB>>>(N, E);

    scatter_kernel<<<(e4 + 1 + TPB - 1) / TPB, TPB>>>(er, ec, ev, E);

    // 3 propagation layers (layer 3 fused with final mean); 4 rows per block
    int spmm_blocks = (N + 3) / 4;
    spmm_h_kernel<<<spmm_blocks, 128>>>((const uint2*)xhp, (uint2*)b1p, N);
    spmm_h_kernel<<<spmm_blocks, 128>>>((const uint2*)b1p, (uint2*)b2p, N);
    spmm_final_kernel<<<spmm_blocks, 128>>>((const uint2*)b2p,
                                            (const float4*)x,
                                            (const uint2*)b1p,
                                            (float4*)d_out, N);
}